// round 10
// baseline (speedup 1.0000x reference)
#include <cuda_runtime.h>
#include <cstdint>

#define BN   2048      // batch rows
#define NL   64        // latent dim
#define NU   16        // nuisance dim
#define NO   2048      // output dim
#define ZS   (NL + NU) // z row stride (80)
#define TM   8         // rows per decoder tile (same nuisance id)
#define NT   512       // decoder threads: thread t owns cols [4t, 4t+4)
#define NBLK 280       // >= max ntiles = sum(ceil(cnt/8)) <= 270; occ 2 => 1 wave

// Prep split: 512 precombine blocks + 8 assign blocks (256 thr each)
#define PRE_BLOCKS 512

// Device-global scratch (no allocation allowed).
// g_hist zero at static init; decoder's last block re-zeroes for next replay.
__device__ float g_Acomb[NU * NL * NO];   // 8 MB: amat_w + amat_site[id]
__device__ int   g_hist[NU];
__device__ int   g_bucket[NU * BN];
__device__ int   g_done = 0;

// ---------- packed f32x2 helpers (Blackwell FFMA2, PTX-only path) ----------
typedef unsigned long long ull;
__device__ __forceinline__ void fma2(ull& d, ull a, ull b) {
    asm("fma.rn.f32x2 %0, %1, %2, %0;" : "+l"(d) : "l"(a), "l"(b));
}
__device__ __forceinline__ ull pack2(float x, float y) {
    ull r; asm("mov.b64 %0, {%1, %2};" : "=l"(r) : "f"(x), "f"(y)); return r;
}
__device__ __forceinline__ void unpack2(ull v, float& x, float& y) {
    asm("mov.b64 {%0, %1}, %2;" : "=f"(x), "=f"(y) : "l"(v));
}
__device__ __forceinline__ float warpMax(float v) {
    #pragma unroll
    for (int o = 16; o > 0; o >>= 1) v = fmaxf(v, __shfl_xor_sync(0xFFFFFFFFu, v, o));
    return v;
}
__device__ __forceinline__ float warpSum(float v) {
    #pragma unroll
    for (int o = 16; o > 0; o >>= 1) v += __shfl_xor_sync(0xFFFFFFFFu, v, o);
    return v;
}

// ---------- kernel 1: prep = precombine ∥ (assign + theta) ----------
__global__ void prep_kernel(const float* __restrict__ z,
                            const float* __restrict__ aw,
                            const float* __restrict__ as,
                            const float* __restrict__ px_r,
                            float* __restrict__ out) {
    const int bid = blockIdx.x;
    const int tid = threadIdx.x;

    if (bid < PRE_BLOCKS) {
        // Acomb = aw + as[id]; 1024 float4 per block, 4 per thread.
        const int per_id = NL * NO / 4;                 // 32768 float4 per id (pow2)
        const float4* as4 = (const float4*)as;
        const float4* aw4 = (const float4*)aw;
        float4* ac4 = (float4*)g_Acomb;
        int base = bid * 1024 + tid;
        #pragma unroll
        for (int k = 0; k < 4; k++) {
            int i = base + k * 256;
            float4 s4 = as4[i];
            float4 w4 = aw4[i & (per_id - 1)];
            float4 o;
            o.x = w4.x + s4.x; o.y = w4.y + s4.y;
            o.z = w4.z + s4.z; o.w = w4.w + s4.w;
            ac4[i] = o;
        }
    } else {
        // assign: one row per thread; also theta = exp(px_r).
        int r = (bid - PRE_BLOCKS) * 256 + tid;         // 0..2047
        out[(size_t)BN * NO + r] = expf(px_r[r]);

        const float4* zn = (const float4*)(z + (size_t)r * ZS + NL);
        float4 a = zn[0], b = zn[1], c = zn[2], d = zn[3];
        float v[NU] = {a.x, a.y, a.z, a.w, b.x, b.y, b.z, b.w,
                       c.x, c.y, c.z, c.w, d.x, d.y, d.z, d.w};
        int best = 0; float bv = v[0];
        #pragma unroll
        for (int j = 1; j < NU; j++)
            if (v[j] > bv) { bv = v[j]; best = j; }     // first-max (jnp.argmax)
        int pos = atomicAdd(&g_hist[best], 1);
        g_bucket[best * BN + pos] = r;
    }
}

// ---------- kernel 2: flat-grid grouped decoder, 2 CTAs/SM ----------
// 280 blocks; block b self-maps to (id, tile) via prefix scan of
// ceil(g_hist[id]/TM). Warp-staggered l-loop + register prefetch to break
// the LDG convoy that capped issue at ~35% in R6/R8.
__global__ __launch_bounds__(NT, 2)
void decoder_kernel(const float* __restrict__ z,
                    const float* __restrict__ size_factor,
                    const float* __restrict__ offsets,
                    float* __restrict__ out) {
    const int tid = threadIdx.x;
    const int wid = tid >> 5;
    const int col = tid * 4;

    __shared__ int s_cnt[NU];
    __shared__ int s_prefix[NU + 1];
    __shared__ __align__(16) float2 zdup[NL][TM];  // (v,v) per (l,row)
    __shared__ float sf_s[TM];
    __shared__ int   rows_s[TM];
    __shared__ float wred[TM * 16];
    __shared__ float rowmax_s[TM];
    __shared__ float rowsum_s[TM];

    // Work-item mapping: prefix over tile counts.
    if (tid < NU) s_cnt[tid] = g_hist[tid];
    __syncthreads();
    if (tid == 0) {
        int acc0 = 0;
        #pragma unroll
        for (int i = 0; i < NU; i++) {
            s_prefix[i] = acc0;
            acc0 += (s_cnt[i] + TM - 1) / TM;
        }
        s_prefix[NU] = acc0;    // ntiles
    }
    __syncthreads();

    const int b = blockIdx.x;
    const int ntiles = s_prefix[NU];

    if (b < ntiles) {
        int id = 0;
        #pragma unroll
        for (int i = 1; i < NU; i++) if (b >= s_prefix[i]) id = i;
        const int tile = b - s_prefix[id];
        const int cnt  = s_cnt[id];
        const int base = tile * TM;

        if (tid < TM) {
            int row = (base + tid < cnt) ? g_bucket[id * BN + base + tid] : -1;
            rows_s[tid] = row;
            sf_s[tid] = (row >= 0) ? size_factor[row] : 1.0f;
        }
        __syncthreads();

        // Stage z duplicated: one element per thread (TM*NL == NT).
        {
            int r = tid & (TM - 1), l = tid / TM;
            int row = rows_s[r];
            float v = (row >= 0) ? z[(size_t)row * ZS + l] : 0.0f;
            zdup[l][r] = make_float2(v, v);
        }
        __syncthreads();

        const float* Ac = g_Acomb + (size_t)id * NL * NO + col;
        const float4 off4 = *(const float4*)(offsets + (size_t)id * NO + col);

        ull acc[TM][2];
        const ull off01 = pack2(off4.x, off4.y);
        const ull off23 = pack2(off4.z, off4.w);
        #pragma unroll
        for (int r = 0; r < TM; r++) { acc[r][0] = off01; acc[r][1] = off23; }

        // Staggered start (per warp AND per block) + depth-1 register prefetch.
        // Accumulation order is a rotation of the l-sum: fp32-benign.
        int l = ((wid + b) & 7) << 3;                   // multiple of 8, 8 phases
        ulonglong2 pn = *(const ulonglong2*)(Ac + (size_t)l * NO);

        #pragma unroll 2
        for (int i = 0; i < NL; i++) {
            const ulonglong2 ap = pn;
            const int lz = l;
            l = (l + 1) & (NL - 1);
            // Prefetch next iteration's A row (last iter re-reads start: harmless).
            pn = *(const ulonglong2*)(Ac + (size_t)l * NO);

            const ulonglong2* zl = (const ulonglong2*)zdup[lz];
            ulonglong2 z0 = zl[0], z1 = zl[1], z2 = zl[2], z3 = zl[3];
            fma2(acc[0][0], ap.x, z0.x);  fma2(acc[0][1], ap.y, z0.x);
            fma2(acc[1][0], ap.x, z0.y);  fma2(acc[1][1], ap.y, z0.y);
            fma2(acc[2][0], ap.x, z1.x);  fma2(acc[2][1], ap.y, z1.x);
            fma2(acc[3][0], ap.x, z1.y);  fma2(acc[3][1], ap.y, z1.y);
            fma2(acc[4][0], ap.x, z2.x);  fma2(acc[4][1], ap.y, z2.x);
            fma2(acc[5][0], ap.x, z2.y);  fma2(acc[5][1], ap.y, z2.y);
            fma2(acc[6][0], ap.x, z3.x);  fma2(acc[6][1], ap.y, z3.x);
            fma2(acc[7][0], ap.x, z3.y);  fma2(acc[7][1], ap.y, z3.y);
        }

        // Unpack logits
        float lv[TM][4];
        #pragma unroll
        for (int r = 0; r < TM; r++) {
            unpack2(acc[r][0], lv[r][0], lv[r][1]);
            unpack2(acc[r][1], lv[r][2], lv[r][3]);
        }

        // Row max (block-wide over 2048 cols, 16 warps)
        #pragma unroll
        for (int r = 0; r < TM; r++) {
            float m = fmaxf(fmaxf(lv[r][0], lv[r][1]), fmaxf(lv[r][2], lv[r][3]));
            m = warpMax(m);
            if ((tid & 31) == 0) wred[r * 16 + wid] = m;
        }
        __syncthreads();
        if (tid < TM) {
            float m = wred[tid * 16];
            #pragma unroll
            for (int w = 1; w < 16; w++) m = fmaxf(m, wred[tid * 16 + w]);
            rowmax_s[tid] = m;
        }
        __syncthreads();

        // Exp + row sum
        #pragma unroll
        for (int r = 0; r < TM; r++) {
            const float rm = rowmax_s[r];
            float e0 = __expf(lv[r][0] - rm);
            float e1 = __expf(lv[r][1] - rm);
            float e2 = __expf(lv[r][2] - rm);
            float e3 = __expf(lv[r][3] - rm);
            lv[r][0] = e0; lv[r][1] = e1; lv[r][2] = e2; lv[r][3] = e3;
            float s = warpSum(e0 + e1 + e2 + e3);
            if ((tid & 31) == 0) wred[r * 16 + wid] = s;
        }
        __syncthreads();
        if (tid < TM) {
            float s = wred[tid * 16];
            #pragma unroll
            for (int w = 1; w < 16; w++) s += wred[tid * 16 + w];
            rowsum_s[tid] = s;
        }
        __syncthreads();

        // Scale and write mu (coalesced float4)
        #pragma unroll
        for (int r = 0; r < TM; r++) {
            int row = rows_s[r];
            if (row >= 0) {
                float sc = sf_s[r] / rowsum_s[r];
                float4 o;
                o.x = lv[r][0] * sc; o.y = lv[r][1] * sc;
                o.z = lv[r][2] * sc; o.w = lv[r][3] * sc;
                *(float4*)(out + (size_t)row * NO + col) = o;
            }
        }
    }

    // Last-block-resets: re-zero g_hist for the next identical replay.
    if (tid == 0) {
        int d = atomicAdd(&g_done, 1);
        if (d == NBLK - 1) {
            g_done = 0;
            #pragma unroll
            for (int i = 0; i < NU; i++) g_hist[i] = 0;
        }
    }
}

extern "C" void kernel_launch(void* const* d_in, const int* in_sizes, int n_in,
                              void* d_out, int out_size) {
    const float* z    = (const float*)d_in[0];
    const float* sf   = (const float*)d_in[1];
    const float* aw   = (const float*)d_in[2];
    const float* as   = (const float*)d_in[3];
    const float* off  = (const float*)d_in[4];
    const float* pxr  = (const float*)d_in[5];
    float* out = (float*)d_out;

    prep_kernel<<<PRE_BLOCKS + 8, 256>>>(z, aw, as, pxr, out);
    decoder_kernel<<<NBLK, NT>>>(z, sf, off, out);
}

// round 13
// speedup vs baseline: 1.7214x; 1.7214x over previous
#include <cuda_runtime.h>
#include <cstdint>

#define BN   2048      // batch rows
#define NL   64        // latent dim
#define NU   16        // nuisance dim
#define NO   2048      // output dim
#define ZS   (NL + NU) // z row stride (80)
#define TM   16        // rows per decoder tile (same nuisance id)
#define NT   512       // decoder threads: thread t owns cols [4t, 4t+4)
#define NBLK 148       // ntiles = sum(ceil(cnt/16)) <= 143 < 148 => single wave

// Prep split: 512 precombine blocks + 8 assign blocks (256 thr each)
#define PRE_BLOCKS 512

// Device-global scratch (no allocation allowed).
// g_hist zero at static init; decoder's last block re-zeroes for next replay.
__device__ float g_Acomb[NU * NL * NO];   // 8 MB: amat_w + amat_site[id]
__device__ int   g_hist[NU];
__device__ int   g_bucket[NU * BN];
__device__ int   g_done = 0;

// ---------- packed f32x2 helpers (Blackwell FFMA2, PTX-only path) ----------
typedef unsigned long long ull;
__device__ __forceinline__ void fma2(ull& d, ull a, ull b) {
    asm("fma.rn.f32x2 %0, %1, %2, %0;" : "+l"(d) : "l"(a), "l"(b));
}
__device__ __forceinline__ ull pack2(float x, float y) {
    ull r; asm("mov.b64 %0, {%1, %2};" : "=l"(r) : "f"(x), "f"(y)); return r;
}
__device__ __forceinline__ void unpack2(ull v, float& x, float& y) {
    asm("mov.b64 {%0, %1}, %2;" : "=f"(x), "=f"(y) : "l"(v));
}
__device__ __forceinline__ float warpMax(float v) {
    #pragma unroll
    for (int o = 16; o > 0; o >>= 1) v = fmaxf(v, __shfl_xor_sync(0xFFFFFFFFu, v, o));
    return v;
}
__device__ __forceinline__ float warpSum(float v) {
    #pragma unroll
    for (int o = 16; o > 0; o >>= 1) v += __shfl_xor_sync(0xFFFFFFFFu, v, o);
    return v;
}

// ---------- kernel 1: prep = precombine ∥ (assign + theta) ----------
__global__ void prep_kernel(const float* __restrict__ z,
                            const float* __restrict__ aw,
                            const float* __restrict__ as,
                            const float* __restrict__ px_r,
                            float* __restrict__ out) {
    const int bid = blockIdx.x;
    const int tid = threadIdx.x;

    if (bid < PRE_BLOCKS) {
        // Acomb = aw + as[id]; 1024 float4 per block, 4 per thread.
        const int per_id = NL * NO / 4;                 // 32768 float4 per id (pow2)
        const float4* as4 = (const float4*)as;
        const float4* aw4 = (const float4*)aw;
        float4* ac4 = (float4*)g_Acomb;
        int base = bid * 1024 + tid;
        #pragma unroll
        for (int k = 0; k < 4; k++) {
            int i = base + k * 256;
            float4 s4 = as4[i];
            float4 w4 = aw4[i & (per_id - 1)];
            float4 o;
            o.x = w4.x + s4.x; o.y = w4.y + s4.y;
            o.z = w4.z + s4.z; o.w = w4.w + s4.w;
            ac4[i] = o;
        }
    } else {
        // assign: one row per thread; also theta = exp(px_r).
        int r = (bid - PRE_BLOCKS) * 256 + tid;         // 0..2047
        out[(size_t)BN * NO + r] = expf(px_r[r]);

        const float4* zn = (const float4*)(z + (size_t)r * ZS + NL);
        float4 a = zn[0], b = zn[1], c = zn[2], d = zn[3];
        float v[NU] = {a.x, a.y, a.z, a.w, b.x, b.y, b.z, b.w,
                       c.x, c.y, c.z, c.w, d.x, d.y, d.z, d.w};
        int best = 0; float bv = v[0];
        #pragma unroll
        for (int j = 1; j < NU; j++)
            if (v[j] > bv) { bv = v[j]; best = j; }     // first-max (jnp.argmax)
        int pos = atomicAdd(&g_hist[best], 1);
        g_bucket[best * BN + pos] = r;
    }
}

// ---------- kernel 2: flat-grid grouped decoder, depth-4 static prefetch ----
// 148 blocks; block b self-maps to (id, tile) via prefix scan of
// ceil(g_hist[id]/TM). Fully unrolled l-loop in groups of 4 with a 4-deep
// register prefetch pipeline; all LDG offsets are compile-time immediates.
__global__ __launch_bounds__(NT, 1)
void decoder_kernel(const float* __restrict__ z,
                    const float* __restrict__ size_factor,
                    const float* __restrict__ offsets,
                    float* __restrict__ out) {
    const int tid = threadIdx.x;
    const int wid = tid >> 5;
    const int col = tid * 4;

    __shared__ int s_cnt[NU];
    __shared__ int s_prefix[NU + 1];
    __shared__ __align__(16) float2 zdup[NL][TM];  // (v,v) per (l,row)
    __shared__ float sf_s[TM];
    __shared__ int   rows_s[TM];
    __shared__ float wred[TM * 16];
    __shared__ float rowmax_s[TM];
    __shared__ float rowsum_s[TM];

    // Work-item mapping: prefix over tile counts.
    if (tid < NU) s_cnt[tid] = g_hist[tid];
    __syncthreads();
    if (tid == 0) {
        int acc0 = 0;
        #pragma unroll
        for (int i = 0; i < NU; i++) {
            s_prefix[i] = acc0;
            acc0 += (s_cnt[i] + TM - 1) / TM;
        }
        s_prefix[NU] = acc0;    // ntiles
    }
    __syncthreads();

    const int b = blockIdx.x;
    const int ntiles = s_prefix[NU];

    if (b < ntiles) {
        int id = 0;
        #pragma unroll
        for (int i = 1; i < NU; i++) if (b >= s_prefix[i]) id = i;
        const int tile = b - s_prefix[id];
        const int cnt  = s_cnt[id];
        const int base = tile * TM;

        if (tid < TM) {
            int row = (base + tid < cnt) ? g_bucket[id * BN + base + tid] : -1;
            rows_s[tid] = row;
            sf_s[tid] = (row >= 0) ? size_factor[row] : 1.0f;
        }
        __syncthreads();

        // Stage z duplicated: zdup[l][r] = (z[row r][l], same); 2 elems/thread.
        #pragma unroll
        for (int i = tid; i < TM * NL; i += NT) {
            int r = i & (TM - 1), l = i >> 4;
            int row = rows_s[r];
            float v = (row >= 0) ? z[(size_t)row * ZS + l] : 0.0f;
            zdup[l][r] = make_float2(v, v);
        }
        __syncthreads();

        const float* Ac = g_Acomb + (size_t)id * NL * NO + col;
        const float4 off4 = *(const float4*)(offsets + (size_t)id * NO + col);

        ull acc[TM][2];
        const ull off01 = pack2(off4.x, off4.y);
        const ull off23 = pack2(off4.z, off4.w);
        #pragma unroll
        for (int r = 0; r < TM; r++) { acc[r][0] = off01; acc[r][1] = off23; }

        // One group of 4 l-steps against prefetched A rows.
        #define STEP(lz, ap) do {                                             \
            const ulonglong2* zl_ = (const ulonglong2*)zdup[(lz)];            \
            _Pragma("unroll")                                                 \
            for (int rp = 0; rp < TM / 2; rp++) {                             \
                ulonglong2 zp = zl_[rp];          /* LDS.128, 2 rows */       \
                fma2(acc[2 * rp][0],     (ap).x, zp.x);                       \
                fma2(acc[2 * rp][1],     (ap).y, zp.x);                       \
                fma2(acc[2 * rp + 1][0], (ap).x, zp.y);                       \
                fma2(acc[2 * rp + 1][1], (ap).y, zp.y);                       \
            } } while (0)

        // Depth-4 prefetch pipeline, fully unrolled (compile-time offsets).
        ulonglong2 nb0 = *(const ulonglong2*)(Ac + 0 * NO);
        ulonglong2 nb1 = *(const ulonglong2*)(Ac + 1 * NO);
        ulonglong2 nb2 = *(const ulonglong2*)(Ac + 2 * NO);
        ulonglong2 nb3 = *(const ulonglong2*)(Ac + 3 * NO);
        #pragma unroll
        for (int g = 0; g < NL / 4; g++) {
            ulonglong2 b0 = nb0, b1 = nb1, b2 = nb2, b3 = nb3;
            if (g < NL / 4 - 1) {
                nb0 = *(const ulonglong2*)(Ac + (size_t)(4 * g + 4) * NO);
                nb1 = *(const ulonglong2*)(Ac + (size_t)(4 * g + 5) * NO);
                nb2 = *(const ulonglong2*)(Ac + (size_t)(4 * g + 6) * NO);
                nb3 = *(const ulonglong2*)(Ac + (size_t)(4 * g + 7) * NO);
            }
            STEP(4 * g + 0, b0);
            STEP(4 * g + 1, b1);
            STEP(4 * g + 2, b2);
            STEP(4 * g + 3, b3);
        }
        #undef STEP

        // Unpack logits
        float lv[TM][4];
        #pragma unroll
        for (int r = 0; r < TM; r++) {
            unpack2(acc[r][0], lv[r][0], lv[r][1]);
            unpack2(acc[r][1], lv[r][2], lv[r][3]);
        }

        // Row max (block-wide over 2048 cols, 16 warps)
        #pragma unroll
        for (int r = 0; r < TM; r++) {
            float m = fmaxf(fmaxf(lv[r][0], lv[r][1]), fmaxf(lv[r][2], lv[r][3]));
            m = warpMax(m);
            if ((tid & 31) == 0) wred[r * 16 + wid] = m;
        }
        __syncthreads();
        if (tid < TM) {
            float m = wred[tid * 16];
            #pragma unroll
            for (int w = 1; w < 16; w++) m = fmaxf(m, wred[tid * 16 + w]);
            rowmax_s[tid] = m;
        }
        __syncthreads();

        // Exp + row sum
        #pragma unroll
        for (int r = 0; r < TM; r++) {
            const float rm = rowmax_s[r];
            float e0 = __expf(lv[r][0] - rm);
            float e1 = __expf(lv[r][1] - rm);
            float e2 = __expf(lv[r][2] - rm);
            float e3 = __expf(lv[r][3] - rm);
            lv[r][0] = e0; lv[r][1] = e1; lv[r][2] = e2; lv[r][3] = e3;
            float s = warpSum(e0 + e1 + e2 + e3);
            if ((tid & 31) == 0) wred[r * 16 + wid] = s;
        }
        __syncthreads();
        if (tid < TM) {
            float s = wred[tid * 16];
            #pragma unroll
            for (int w = 1; w < 16; w++) s += wred[tid * 16 + w];
            rowsum_s[tid] = s;
        }
        __syncthreads();

        // Scale and write mu (coalesced float4)
        #pragma unroll
        for (int r = 0; r < TM; r++) {
            int row = rows_s[r];
            if (row >= 0) {
                float sc = sf_s[r] / rowsum_s[r];
                float4 o;
                o.x = lv[r][0] * sc; o.y = lv[r][1] * sc;
                o.z = lv[r][2] * sc; o.w = lv[r][3] * sc;
                *(float4*)(out + (size_t)row * NO + col) = o;
            }
        }
    }

    // Last-block-resets: re-zero g_hist for the next identical replay.
    if (tid == 0) {
        int d = atomicAdd(&g_done, 1);
        if (d == NBLK - 1) {
            g_done = 0;
            #pragma unroll
            for (int i = 0; i < NU; i++) g_hist[i] = 0;
        }
    }
}

extern "C" void kernel_launch(void* const* d_in, const int* in_sizes, int n_in,
                              void* d_out, int out_size) {
    const float* z    = (const float*)d_in[0];
    const float* sf   = (const float*)d_in[1];
    const float* aw   = (const float*)d_in[2];
    const float* as   = (const float*)d_in[3];
    const float* off  = (const float*)d_in[4];
    const float* pxr  = (const float*)d_in[5];
    float* out = (float*)d_out;

    prep_kernel<<<PRE_BLOCKS + 8, 256>>>(z, aw, as, pxr, out);
    decoder_kernel<<<NBLK, NT>>>(z, sf, off, out);
}

// round 14
// speedup vs baseline: 1.8312x; 1.0638x over previous
#include <cuda_runtime.h>
#include <cstdint>

#define BN   2048      // batch rows
#define NL   64        // latent dim
#define NU   16        // nuisance dim
#define NO   2048      // output dim
#define ZS   (NL + NU) // z row stride (80)
#define TM   16        // rows per decoder tile (same nuisance id)
#define NT   512       // decoder threads: thread t owns 4 rotated cols
#define NBLK 148       // ntiles = sum(ceil(cnt/16)) <= 143 < 148 => single wave

// Prep split: 512 precombine blocks + 8 assign blocks (256 thr each)
#define PRE_BLOCKS 512

// Device-global scratch (no allocation allowed).
// g_hist zero at static init; decoder's last block re-zeroes for next replay.
__device__ float g_Acomb[NU * NL * NO];   // 8 MB: amat_w + amat_site[id]
__device__ int   g_hist[NU];
__device__ int   g_bucket[NU * BN];
__device__ int   g_done = 0;

// ---------- packed f32x2 helpers (Blackwell FFMA2, PTX-only path) ----------
typedef unsigned long long ull;
__device__ __forceinline__ void fma2(ull& d, ull a, ull b) {
    asm("fma.rn.f32x2 %0, %1, %2, %0;" : "+l"(d) : "l"(a), "l"(b));
}
__device__ __forceinline__ ull pack2(float x, float y) {
    ull r; asm("mov.b64 %0, {%1, %2};" : "=l"(r) : "f"(x), "f"(y)); return r;
}
__device__ __forceinline__ void unpack2(ull v, float& x, float& y) {
    asm("mov.b64 {%0, %1}, %2;" : "=f"(x), "=f"(y) : "l"(v));
}
__device__ __forceinline__ float warpMax(float v) {
    #pragma unroll
    for (int o = 16; o > 0; o >>= 1) v = fmaxf(v, __shfl_xor_sync(0xFFFFFFFFu, v, o));
    return v;
}
__device__ __forceinline__ float warpSum(float v) {
    #pragma unroll
    for (int o = 16; o > 0; o >>= 1) v += __shfl_xor_sync(0xFFFFFFFFu, v, o);
    return v;
}

// ---------- kernel 1: prep = precombine ∥ (assign + theta) ----------
__global__ void prep_kernel(const float* __restrict__ z,
                            const float* __restrict__ aw,
                            const float* __restrict__ as,
                            const float* __restrict__ px_r,
                            float* __restrict__ out) {
    const int bid = blockIdx.x;
    const int tid = threadIdx.x;

    if (bid < PRE_BLOCKS) {
        // Acomb = aw + as[id]; 1024 float4 per block, 4 per thread.
        const int per_id = NL * NO / 4;                 // 32768 float4 per id (pow2)
        const float4* as4 = (const float4*)as;
        const float4* aw4 = (const float4*)aw;
        float4* ac4 = (float4*)g_Acomb;
        int base = bid * 1024 + tid;
        #pragma unroll
        for (int k = 0; k < 4; k++) {
            int i = base + k * 256;
            float4 s4 = as4[i];
            float4 w4 = aw4[i & (per_id - 1)];
            float4 o;
            o.x = w4.x + s4.x; o.y = w4.y + s4.y;
            o.z = w4.z + s4.z; o.w = w4.w + s4.w;
            ac4[i] = o;
        }
    } else {
        // assign: one row per thread; also theta = exp(px_r).
        int r = (bid - PRE_BLOCKS) * 256 + tid;         // 0..2047
        out[(size_t)BN * NO + r] = expf(px_r[r]);

        const float4* zn = (const float4*)(z + (size_t)r * ZS + NL);
        float4 a = zn[0], b = zn[1], c = zn[2], d = zn[3];
        float v[NU] = {a.x, a.y, a.z, a.w, b.x, b.y, b.z, b.w,
                       c.x, c.y, c.z, c.w, d.x, d.y, d.z, d.w};
        int best = 0; float bv = v[0];
        #pragma unroll
        for (int j = 1; j < NU; j++)
            if (v[j] > bv) { bv = v[j]; best = j; }     // first-max (jnp.argmax)
        int pos = atomicAdd(&g_hist[best], 1);
        g_bucket[best * BN + pos] = r;
    }
}

// ---------- kernel 2: flat-grid grouped decoder ----------
// 148 blocks; block b self-maps to (id, tile) via prefix scan of
// ceil(g_hist[id]/TM). Depth-4 static register prefetch (immediate offsets)
// + per-block COLUMN ROTATION ((b&7)*256 cols = 1KB, flips L2-hash bit 10)
// to decorrelate same-id blocks' L2 slice access and break the LTS convoy.
__global__ __launch_bounds__(NT, 1)
void decoder_kernel(const float* __restrict__ z,
                    const float* __restrict__ size_factor,
                    const float* __restrict__ offsets,
                    float* __restrict__ out) {
    const int tid = threadIdx.x;
    const int wid = tid >> 5;

    __shared__ int s_cnt[NU];
    __shared__ int s_prefix[NU + 1];
    __shared__ __align__(16) float2 zdup[NL][TM];  // (v,v) per (l,row)
    __shared__ float sf_s[TM];
    __shared__ int   rows_s[TM];
    __shared__ float wred[TM * 16];
    __shared__ float rowmax_s[TM];
    __shared__ float rowsum_s[TM];

    // Work-item mapping: prefix over tile counts.
    if (tid < NU) s_cnt[tid] = g_hist[tid];
    __syncthreads();
    if (tid == 0) {
        int acc0 = 0;
        #pragma unroll
        for (int i = 0; i < NU; i++) {
            s_prefix[i] = acc0;
            acc0 += (s_cnt[i] + TM - 1) / TM;
        }
        s_prefix[NU] = acc0;    // ntiles
    }
    __syncthreads();

    const int b = blockIdx.x;
    const int ntiles = s_prefix[NU];

    // Rotated column base: bijection t -> (4t + rot) mod 2048, rot mult. of 256.
    const int col = ((tid * 4) + ((b & 7) << 8)) & (NO - 1);

    if (b < ntiles) {
        int id = 0;
        #pragma unroll
        for (int i = 1; i < NU; i++) if (b >= s_prefix[i]) id = i;
        const int tile = b - s_prefix[id];
        const int cnt  = s_cnt[id];
        const int base = tile * TM;

        if (tid < TM) {
            int row = (base + tid < cnt) ? g_bucket[id * BN + base + tid] : -1;
            rows_s[tid] = row;
            sf_s[tid] = (row >= 0) ? size_factor[row] : 1.0f;
        }
        __syncthreads();

        // Stage z duplicated: zdup[l][r] = (z[row r][l], same); 2 elems/thread.
        #pragma unroll
        for (int i = tid; i < TM * NL; i += NT) {
            int r = i & (TM - 1), l = i >> 4;
            int row = rows_s[r];
            float v = (row >= 0) ? z[(size_t)row * ZS + l] : 0.0f;
            zdup[l][r] = make_float2(v, v);
        }
        __syncthreads();

        const float* Ac = g_Acomb + (size_t)id * NL * NO + col;
        const float4 off4 = *(const float4*)(offsets + (size_t)id * NO + col);

        ull acc[TM][2];
        const ull off01 = pack2(off4.x, off4.y);
        const ull off23 = pack2(off4.z, off4.w);
        #pragma unroll
        for (int r = 0; r < TM; r++) { acc[r][0] = off01; acc[r][1] = off23; }

        // One group of 4 l-steps against prefetched A rows.
        #define STEP(lz, ap) do {                                             \
            const ulonglong2* zl_ = (const ulonglong2*)zdup[(lz)];            \
            _Pragma("unroll")                                                 \
            for (int rp = 0; rp < TM / 2; rp++) {                             \
                ulonglong2 zp = zl_[rp];          /* LDS.128, 2 rows */       \
                fma2(acc[2 * rp][0],     (ap).x, zp.x);                       \
                fma2(acc[2 * rp][1],     (ap).y, zp.x);                       \
                fma2(acc[2 * rp + 1][0], (ap).x, zp.y);                       \
                fma2(acc[2 * rp + 1][1], (ap).y, zp.y);                       \
            } } while (0)

        // Depth-4 prefetch pipeline, fully unrolled (compile-time offsets).
        ulonglong2 nb0 = *(const ulonglong2*)(Ac + 0 * NO);
        ulonglong2 nb1 = *(const ulonglong2*)(Ac + 1 * NO);
        ulonglong2 nb2 = *(const ulonglong2*)(Ac + 2 * NO);
        ulonglong2 nb3 = *(const ulonglong2*)(Ac + 3 * NO);
        #pragma unroll
        for (int g = 0; g < NL / 4; g++) {
            ulonglong2 b0 = nb0, b1 = nb1, b2 = nb2, b3 = nb3;
            if (g < NL / 4 - 1) {
                nb0 = *(const ulonglong2*)(Ac + (size_t)(4 * g + 4) * NO);
                nb1 = *(const ulonglong2*)(Ac + (size_t)(4 * g + 5) * NO);
                nb2 = *(const ulonglong2*)(Ac + (size_t)(4 * g + 6) * NO);
                nb3 = *(const ulonglong2*)(Ac + (size_t)(4 * g + 7) * NO);
            }
            STEP(4 * g + 0, b0);
            STEP(4 * g + 1, b1);
            STEP(4 * g + 2, b2);
            STEP(4 * g + 3, b3);
        }
        #undef STEP

        // Unpack logits
        float lv[TM][4];
        #pragma unroll
        for (int r = 0; r < TM; r++) {
            unpack2(acc[r][0], lv[r][0], lv[r][1]);
            unpack2(acc[r][1], lv[r][2], lv[r][3]);
        }

        // Row max (block-wide over 2048 cols, 16 warps)
        #pragma unroll
        for (int r = 0; r < TM; r++) {
            float m = fmaxf(fmaxf(lv[r][0], lv[r][1]), fmaxf(lv[r][2], lv[r][3]));
            m = warpMax(m);
            if ((tid & 31) == 0) wred[r * 16 + wid] = m;
        }
        __syncthreads();
        if (tid < TM) {
            float m = wred[tid * 16];
            #pragma unroll
            for (int w = 1; w < 16; w++) m = fmaxf(m, wred[tid * 16 + w]);
            rowmax_s[tid] = m;
        }
        __syncthreads();

        // Exp + row sum
        #pragma unroll
        for (int r = 0; r < TM; r++) {
            const float rm = rowmax_s[r];
            float e0 = __expf(lv[r][0] - rm);
            float e1 = __expf(lv[r][1] - rm);
            float e2 = __expf(lv[r][2] - rm);
            float e3 = __expf(lv[r][3] - rm);
            lv[r][0] = e0; lv[r][1] = e1; lv[r][2] = e2; lv[r][3] = e3;
            float s = warpSum(e0 + e1 + e2 + e3);
            if ((tid & 31) == 0) wred[r * 16 + wid] = s;
        }
        __syncthreads();
        if (tid < TM) {
            float s = wred[tid * 16];
            #pragma unroll
            for (int w = 1; w < 16; w++) s += wred[tid * 16 + w];
            rowsum_s[tid] = s;
        }
        __syncthreads();

        // Scale and write mu (coalesced float4, rotated but contiguous)
        #pragma unroll
        for (int r = 0; r < TM; r++) {
            int row = rows_s[r];
            if (row >= 0) {
                float sc = sf_s[r] / rowsum_s[r];
                float4 o;
                o.x = lv[r][0] * sc; o.y = lv[r][1] * sc;
                o.z = lv[r][2] * sc; o.w = lv[r][3] * sc;
                *(float4*)(out + (size_t)row * NO + col) = o;
            }
        }
    }

    // Last-block-resets: re-zero g_hist for the next identical replay.
    if (tid == 0) {
        int d = atomicAdd(&g_done, 1);
        if (d == NBLK - 1) {
            g_done = 0;
            #pragma unroll
            for (int i = 0; i < NU; i++) g_hist[i] = 0;
        }
    }
}

extern "C" void kernel_launch(void* const* d_in, const int* in_sizes, int n_in,
                              void* d_out, int out_size) {
    const float* z    = (const float*)d_in[0];
    const float* sf   = (const float*)d_in[1];
    const float* aw   = (const float*)d_in[2];
    const float* as   = (const float*)d_in[3];
    const float* off  = (const float*)d_in[4];
    const float* pxr  = (const float*)d_in[5];
    float* out = (float*)d_out;

    prep_kernel<<<PRE_BLOCKS + 8, 256>>>(z, aw, as, pxr, out);
    decoder_kernel<<<NBLK, NT>>>(z, sf, off, out);
}